// round 13
// baseline (speedup 1.0000x reference)
#include <cuda_runtime.h>

// Problem constants
#define MAXN 100000
#define MAXE 1600000
#define MAXNT 784          // max node tiles of 128
#define FEAT 64
#define DN 128             // nodes per tile
#define AGP 132            // s_agg stride (16B-aligned rows; gather STS 8-way max)
#define SCAN_CHUNK 2048
#define MAXBLK 64

typedef unsigned long long ull;

// Scratch (__device__ globals; allocation-free rule). Referenced ONLY from
// device code (flag-selected) — never passed as kernel args from host.
__device__ __align__(16) float g_h1  [MAXN * FEAT];       // layer-0 out, [n][k]
__device__ __align__(16) float g_xT  [MAXNT * 64 * 128];  // x transposed tiles
__device__ __align__(16) float g_h1T [MAXNT * 64 * 128];  // h1 transposed tiles
__device__ __align__(16) float g_wT  [6 * 64 * 64];       // wl0,wr0,ws0,wl1,wr1,ws1 [k][d]
__device__ int g_cnt[MAXN];
__device__ int g_off[MAXN + 1];
__device__ int g_cur[MAXN];
__device__ int g_csr_src[MAXE];
__device__ int g_bsum[MAXBLK];
__device__ int g_bar;

// ---- packed f32x2 helpers (Blackwell PTX) ----------------------------------
__device__ __forceinline__ void fma2(ull& acc, ull av, ull wv)
{
    asm("fma.rn.f32x2 %0, %1, %2, %0;" : "+l"(acc) : "l"(av), "l"(wv));
}
__device__ __forceinline__ ull dup2(float w)
{
    ull r; asm("mov.b64 %0, {%1, %1};" : "=l"(r) : "f"(w)); return r;
}
__device__ __forceinline__ void unpk(float& lo, float& hi, ull v)
{
    asm("mov.b64 {%0, %1}, %2;" : "=f"(lo), "=f"(hi) : "l"(v));
}
__device__ __forceinline__ ull pk2(float lo, float hi)
{
    ull r; asm("mov.b64 %0, {%1, %2};" : "=l"(r) : "f"(lo), "f"(hi)); return r;
}

// ---- cp.async helpers -------------------------------------------------------
__device__ __forceinline__ void cp16(void* dst_smem, const void* src_gmem)
{
    unsigned u = (unsigned)__cvta_generic_to_shared(dst_smem);
    asm volatile("cp.async.cg.shared.global [%0], [%1], 16;"
                 :: "r"(u), "l"(src_gmem) : "memory");
}
#define CP_COMMIT() asm volatile("cp.async.commit_group;" ::: "memory")
#define CP_WAIT(n)  asm volatile("cp.async.wait_group %0;" :: "n"(n) : "memory")
#define BAR_COMPUTE() asm volatile("bar.sync 1, 128;" ::: "memory")

// ---------------------------------------------------------------------------
// Prep (unchanged, proven): tile transpose [n][64] -> [t][k][128], plus
// (doExtra) grid-stride edge histogram and 6 weight transposes into g_wT.
// ---------------------------------------------------------------------------
__global__ void prep_kernel(const float* __restrict__ x, int N, int NT,
                            const int* __restrict__ hdst, int E,
                            const float* __restrict__ w0, const float* __restrict__ w1,
                            const float* __restrict__ w2, const float* __restrict__ w3,
                            const float* __restrict__ w4, const float* __restrict__ w5)
{
    __shared__ float s[64 * 129];
    int tid = threadIdx.x;
    int t   = blockIdx.x;

    {   // histogram (grid-stride over all blocks)
        int gs = gridDim.x * blockDim.x;
        for (int e = blockIdx.x * blockDim.x + tid; e < E; e += gs)
            atomicAdd(&g_cnt[hdst[e]], 1);
    }

    if (t < NT) {
        for (int i = tid; i < 2048; i += 256) {
            int n = i >> 4, kq = i & 15;
            int gn = t * DN + n;
            float4 v = make_float4(0.f, 0.f, 0.f, 0.f);
            if (gn < N) v = *(const float4*)&x[gn * FEAT + kq * 4];
            s[(4 * kq + 0) * 129 + n] = v.x;
            s[(4 * kq + 1) * 129 + n] = v.y;
            s[(4 * kq + 2) * 129 + n] = v.z;
            s[(4 * kq + 3) * 129 + n] = v.w;
        }
        __syncthreads();
        float* dst = g_xT + (size_t)t * 8192;
        for (int i = tid; i < 8192; i += 256)
            dst[i] = s[(i >> 7) * 129 + (i & 127)];
    } else {
        int m = t - NT;     // weight transpose 0..5
        if (m < 6) {
            const float* w = (m == 0) ? w0 : (m == 1) ? w1 : (m == 2) ? w2
                           : (m == 3) ? w3 : (m == 4) ? w4 : w5;
            for (int i = tid; i < 4096; i += 256) {
                int d = i >> 6, k = i & 63;
                s[k * 65 + d] = w[i];
            }
            __syncthreads();
            for (int i = tid; i < 4096; i += 256)
                g_wT[m * 4096 + i] = s[(i >> 6) * 65 + (i & 63)];
        }
    }
}

// Software grid barrier (49 blocks co-resident on 148 SMs).
__device__ __forceinline__ void grid_bar(int target)
{
    __syncthreads();
    if (threadIdx.x == 0) {
        __threadfence();
        atomicAdd(&g_bar, 1);
        while (atomicAdd(&g_bar, 0) < target) { }
    }
    __syncthreads();
}

// ---------------------------------------------------------------------------
// Scan + fill (unchanged, proven): exclusive scan (zeroing g_cnt -> restores
// invariant) -> offsets (+g_off[N]=E) -> bucket edges. Block 0 resets g_bar.
// ---------------------------------------------------------------------------
__global__ void scanfill_kernel(const int* __restrict__ src,
                                const int* __restrict__ dst,
                                int N, int E, int nb)
{
    __shared__ int s_sum[256];
    int t = threadIdx.x;

    int base = blockIdx.x * SCAN_CHUNK + t * 8;
    int v[8], tot = 0;
#pragma unroll
    for (int j = 0; j < 8; j++) {
        int idx = base + j;
        if (idx < N) { v[j] = g_cnt[idx]; g_cnt[idx] = 0; }
        else v[j] = 0;
        tot += v[j];
    }
    s_sum[t] = tot;
    __syncthreads();
    for (int off = 1; off < 256; off <<= 1) {
        int xv = (t >= off) ? s_sum[t - off] : 0;
        __syncthreads();
        s_sum[t] += xv;
        __syncthreads();
    }
    if (t == 255) g_bsum[blockIdx.x] = s_sum[255];
    int run = s_sum[t] - tot;

    grid_bar(nb);

    int bpre = 0;
    for (int b = 0; b < (int)blockIdx.x; b++) bpre += g_bsum[b];
    run += bpre;
#pragma unroll
    for (int j = 0; j < 8; j++) {
        int idx = base + j;
        if (idx < N) { g_off[idx] = run; g_cur[idx] = run; }
        run += v[j];
    }
    if (blockIdx.x == nb - 1 && t == 255) g_off[N] = E;

    grid_bar(2 * nb);

    int tg = blockIdx.x * blockDim.x + t;
    int T  = gridDim.x * blockDim.x;
    for (int eb = tg * 8; eb < E; eb += T * 8) {
#pragma unroll
        for (int j = 0; j < 8; j++) {
            int e = eb + j;
            if (e < E) {
                int p = atomicAdd(&g_cur[dst[e]], 1);
                g_csr_src[p] = src[e];
            }
        }
    }
    if (blockIdx.x == 0 && t == 0) g_bar = 0;   // restore invariant
}

// ---------------------------------------------------------------------------
// Work-stealing gather into the block's s_agg tile. One warp per node grab;
// lane covers feats (2l, 2l+1) as float2; writes mean TRANSPOSED [k][AGP].
// ---------------------------------------------------------------------------
__device__ void gather_steal(const float2* __restrict__ h2, int base, int N,
                             float* __restrict__ sagg, int* __restrict__ ctr)
{
    int lane = threadIdx.x & 31;
    for (;;) {
        int n = 0;
        if (lane == 0) n = atomicAdd(ctr, 1);
        n = __shfl_sync(0xffffffffu, n, 0);
        if (n >= DN) break;
        int gn = base + n;
        float ax = 0.f, ay = 0.f;
        int deg = 0;
        if (gn < N) {
            int start = g_off[gn];
            deg = g_off[gn + 1] - start;
            int i = 0;
            for (; i + 8 <= deg; i += 8) {
                int sidx[8];
#pragma unroll
                for (int j = 0; j < 8; j++) sidx[j] = g_csr_src[start + i + j];
                float2 v[8];
#pragma unroll
                for (int j = 0; j < 8; j++) v[j] = h2[sidx[j] * 32 + lane];
                ax += ((v[0].x + v[1].x) + (v[2].x + v[3].x))
                    + ((v[4].x + v[5].x) + (v[6].x + v[7].x));
                ay += ((v[0].y + v[1].y) + (v[2].y + v[3].y))
                    + ((v[4].y + v[5].y) + (v[6].y + v[7].y));
            }
            for (; i < deg; i++) {
                int sidx = g_csr_src[start + i];
                float2 v = h2[sidx * 32 + lane];
                ax += v.x; ay += v.y;
            }
        }
        float inv = 1.f / fmaxf((float)deg, 1.f);
        sagg[(2 * lane) * AGP + n]     = ax * inv;
        sagg[(2 * lane + 1) * AGP + n] = ay * inv;
    }
}

// One GEMM phase: acc[8][4] += actT(k x n, stride) @ w(k x d). Thread: 8d x 8n.
__device__ __forceinline__ void gemm_phase(const float* __restrict__ act, int stride,
                                           const float* __restrict__ w,
                                           ull acc[8][4], int d0, int n0)
{
#pragma unroll 4
    for (int k = 0; k < 64; k++) {
        float4 wa = *(const float4*)&w[k * 64 + d0];
        float4 wb = *(const float4*)&w[k * 64 + d0 + 4];
        ull wd[8];
        wd[0] = dup2(wa.x); wd[1] = dup2(wa.y); wd[2] = dup2(wa.z); wd[3] = dup2(wa.w);
        wd[4] = dup2(wb.x); wd[5] = dup2(wb.y); wd[6] = dup2(wb.z); wd[7] = dup2(wb.w);
        longlong2 p01 = *(const longlong2*)&act[k * stride + n0];
        longlong2 p23 = *(const longlong2*)&act[k * stride + n0 + 4];
        ull av[4];
        av[0] = (ull)p01.x; av[1] = (ull)p01.y;
        av[2] = (ull)p23.x; av[3] = (ull)p23.y;
#pragma unroll
        for (int dd = 0; dd < 8; dd++)
#pragma unroll
            for (int p = 0; p < 4; p++)
                fma2(acc[dd][p], av[p], wd[dd]);
    }
}

// ---------------------------------------------------------------------------
// Fused layer kernel: per 128-node tile, warps 0-3 compute / warps 4-7 gather.
// Phase order (commutative sums): h@wr  -> [gather done] -> agg@wl -> +bl,
// PReLU (regs) -> x@ws -> +bs. Single packed accumulator set.
// Layer 0 epilogue dual-writes h1 natural + h1T tiles for layer 1.
// smem: act 32KB + s_agg 33KB + wA/wB 32KB = 99.3KB -> 2 blocks/SM.
// ---------------------------------------------------------------------------
__global__ void __launch_bounds__(256, 2) layer_kernel(
    const float* __restrict__ x,
    const float* __restrict__ b_l, const float* __restrict__ b_skip,
    const float* __restrict__ a,
    float* __restrict__ out, int N, int layer)
{
    extern __shared__ __align__(16) float sm[];
    float* act  = sm;                    // [64][128]
    float* sagg = sm + 8192;             // [64][AGP]
    float* wA   = sagg + 64 * AGP;       // [64][64]
    float* wB   = wA + 4096;             // [64][64]
    int*   ctr  = (int*)(wB + 4096);

    int tid  = threadIdx.x;
    int t    = blockIdx.x;
    int base = t * DN;

    const float*  hnat = layer ? g_h1 : x;                       // gather source
    const float2* h2   = (const float2*)hnat;
    const float*  hTt  = (layer ? g_h1T : g_xT) + (size_t)t * 8192;
    const float*  xTt  = g_xT + (size_t)t * 8192;
    const float*  wl   = g_wT + layer * 3 * 4096;
    const float*  wr   = wl + 4096;
    const float*  ws   = wl + 8192;

    if (tid == 0) *ctr = 0;
    __syncthreads();

    bool isCompute = (tid < 128);
    int d0 = 0, n0 = 0;
    ull acc[8][4];

    if (isCompute) {
        d0 = (tid & 7) * 8;       // 8 consecutive output features
        n0 = (tid >> 3) * 8;      // 8 nodes (4 f32x2 pairs)

        // stage act<-hT + wA<-wr (g1); wB<-wl (g2)
        for (int i = tid; i < 2048; i += 128) cp16(&act[i * 4], &hTt[i * 4]);
        for (int i = tid; i < 1024; i += 128) cp16(&wA[i * 4], &wr[i * 4]);
        CP_COMMIT();                                  // g1
        for (int i = tid; i < 1024; i += 128) cp16(&wB[i * 4], &wl[i * 4]);
        CP_COMMIT();                                  // g2

#pragma unroll
        for (int dd = 0; dd < 8; dd++)
#pragma unroll
            for (int p = 0; p < 4; p++) acc[dd][p] = 0ULL;

        // ---- phase wr: h @ wr (gather warps run concurrently) ----
        CP_WAIT(1);          // g1 complete
        BAR_COMPUTE();       // act/wA visible to all compute threads
        gemm_phase(act, 128, wA, acc, d0, n0);
        BAR_COMPUTE();       // all done reading act/wA before restage

        // stage phase-ws inputs (g3): layer1 restages act<-xT; wA<-ws
        if (layer) {
            for (int i = tid; i < 2048; i += 128) cp16(&act[i * 4], &xTt[i * 4]);
        }
        for (int i = tid; i < 1024; i += 128) cp16(&wA[i * 4], &ws[i * 4]);
        CP_COMMIT();                                  // g3
        CP_WAIT(1);          // g1,g2 complete (wB=wl staged); g3 may pend
    }

    // all 8 warps: finish the tile's aggregation (compute warps join late)
    gather_steal(h2, base, N, sagg, ctr);
    __syncthreads();         // s_agg complete; wB visible (wait+barrier)

    if (isCompute) {
        // ---- phase wl: agg @ wl ----
        gemm_phase(sagg, AGP, wB, acc, d0, n0);

        // + bl, PReLU in registers
        float blv[8], apv[8];
#pragma unroll
        for (int dd = 0; dd < 8; dd++) { blv[dd] = b_l[d0 + dd]; apv[dd] = a[d0 + dd]; }
#pragma unroll
        for (int dd = 0; dd < 8; dd++)
#pragma unroll
            for (int p = 0; p < 4; p++) {
                float lo, hi;
                unpk(lo, hi, acc[dd][p]);
                lo += blv[dd]; hi += blv[dd];
                lo = (lo >= 0.f) ? lo : apv[dd] * lo;
                hi = (hi >= 0.f) ? hi : apv[dd] * hi;
                acc[dd][p] = pk2(lo, hi);
            }

        // ---- phase ws: x @ ws ----
        CP_WAIT(0);          // g3 complete (own)
        BAR_COMPUTE();       // act(xT)/wA(ws) visible
        gemm_phase(act, 128, wA, acc, d0, n0);

        // epilogue: + bs; write natural [n][k]; layer0 also writes h1T tiles
        float bsv[8];
#pragma unroll
        for (int dd = 0; dd < 8; dd++) bsv[dd] = b_skip[d0 + dd];
        float* dstp = layer ? out : g_h1;
        float* hTo  = g_h1T + (size_t)t * 8192;
#pragma unroll
        for (int p = 0; p < 4; p++) {
            float lo[8], hi[8];
#pragma unroll
            for (int dd = 0; dd < 8; dd++) {
                unpk(lo[dd], hi[dd], acc[dd][p]);
                lo[dd] += bsv[dd]; hi[dd] += bsv[dd];
            }
            int nA = n0 + 2 * p, nB = n0 + 2 * p + 1;
            if (base + nA < N) {
                *(float4*)&dstp[(base + nA) * FEAT + d0]     = make_float4(lo[0], lo[1], lo[2], lo[3]);
                *(float4*)&dstp[(base + nA) * FEAT + d0 + 4] = make_float4(lo[4], lo[5], lo[6], lo[7]);
            }
            if (base + nB < N) {
                *(float4*)&dstp[(base + nB) * FEAT + d0]     = make_float4(hi[0], hi[1], hi[2], hi[3]);
                *(float4*)&dstp[(base + nB) * FEAT + d0 + 4] = make_float4(hi[4], hi[5], hi[6], hi[7]);
            }
            if (layer == 0) {
#pragma unroll
                for (int dd = 0; dd < 8; dd++) {
                    float2 pr; pr.x = lo[dd]; pr.y = hi[dd];
                    *(float2*)&hTo[(d0 + dd) * 128 + nA] = pr;
                }
            }
        }
    }
}

// ---------------------------------------------------------------------------
// Launch sequence: 4 launches. Index 3 (ncu profiled slot) = layer 1.
// ---------------------------------------------------------------------------
extern "C" void kernel_launch(void* const* d_in, const int* in_sizes, int n_in,
                              void* d_out, int out_size)
{
    const float* x  = (const float*)d_in[0];
    const int*   ei = (const int*)d_in[1];   // int32 (JAX x64 disabled)
    int N = in_sizes[0] / FEAT;
    int E = in_sizes[1] / 2;
    const int* src = ei;
    const int* dst = ei + E;

    const float* w_l0    = (const float*)d_in[2];
    const float* b_l0    = (const float*)d_in[3];
    const float* w_r0    = (const float*)d_in[4];
    const float* w_skip0 = (const float*)d_in[5];
    const float* b_skip0 = (const float*)d_in[6];
    const float* a0      = (const float*)d_in[7];
    const float* w_l1    = (const float*)d_in[8];
    const float* b_l1    = (const float*)d_in[9];
    const float* w_r1    = (const float*)d_in[10];
    const float* w_skip1 = (const float*)d_in[11];
    const float* b_skip1 = (const float*)d_in[12];
    const float* a1      = (const float*)d_in[13];
    float* out = (float*)d_out;

    // smem: act 32768 + sagg 33792 + wA 16384 + wB 16384 + ctr pad 32
    size_t lsmem = 32768 + (size_t)64 * AGP * 4 + 16384 + 16384 + 32;
    cudaFuncSetAttribute(layer_kernel, cudaFuncAttributeMaxDynamicSharedMemorySize,
                         (int)lsmem);

    int NT = (N + DN - 1) / DN;                   // 782
    int nb = (N + SCAN_CHUNK - 1) / SCAN_CHUNK;   // 49

    prep_kernel<<<NT + 6, 256>>>(x, N, NT, dst, E,                       // 0
                                 w_l0, w_r0, w_skip0, w_l1, w_r1, w_skip1);
    scanfill_kernel<<<nb, 256>>>(src, dst, N, E, nb);                    // 1

    layer_kernel<<<NT, 256, lsmem>>>(x, b_l0, b_skip0, a0, out, N, 0);   // 2
    layer_kernel<<<NT, 256, lsmem>>>(x, b_l1, b_skip1, a1, out, N, 1);   // 3 <- profiled
}

// round 14
// speedup vs baseline: 1.3926x; 1.3926x over previous
#include <cuda_runtime.h>

// Problem constants
#define MAXN 100000
#define MAXE 1600000
#define MAXNT 784          // max node tiles of 128
#define FEAT 64
#define DN 128             // nodes per dense block / tile
#define SCAN_CHUNK 2048
#define MAXBLK 64

typedef unsigned long long ull;

// Scratch (__device__ globals; allocation-free rule). Referenced ONLY from
// device code — never passed as kernel args from host.
__device__ __align__(16) float g_h1  [MAXN * FEAT];       // layer-0 out, [n][k]
__device__ __align__(16) float g_xT  [MAXNT * 64 * 128];  // x transposed tiles
__device__ __align__(16) float g_h1T [MAXNT * 64 * 128];  // h1 transposed tiles
__device__ __align__(16) float g_aggT[MAXNT * 64 * 128];  // agg transposed tiles
__device__ __align__(16) float g_wT  [6 * 64 * 64];       // wl0,wr0,ws0,wl1,wr1,ws1 [k][d]
__device__ int g_cnt[MAXN];
__device__ int g_off[MAXN + 1];
__device__ int g_cur[MAXN];
__device__ int g_csr_src[MAXE];
__device__ int g_bsum[MAXBLK];
__device__ int g_bar;

// ---- packed f32x2 helpers (Blackwell PTX) ----------------------------------
__device__ __forceinline__ void fma2(ull& acc, ull av, ull wv)
{
    asm("fma.rn.f32x2 %0, %1, %2, %0;" : "+l"(acc) : "l"(av), "l"(wv));
}
__device__ __forceinline__ ull dup2(float w)
{
    ull r; asm("mov.b64 %0, {%1, %1};" : "=l"(r) : "f"(w)); return r;
}
__device__ __forceinline__ void unpk(float& lo, float& hi, ull v)
{
    asm("mov.b64 {%0, %1}, %2;" : "=f"(lo), "=f"(hi) : "l"(v));
}
__device__ __forceinline__ ull pk2(float lo, float hi)
{
    ull r; asm("mov.b64 %0, {%1, %2};" : "=l"(r) : "f"(lo), "f"(hi)); return r;
}

// ---- cp.async helpers -------------------------------------------------------
__device__ __forceinline__ void cp16(void* dst_smem, const void* src_gmem)
{
    unsigned u = (unsigned)__cvta_generic_to_shared(dst_smem);
    asm volatile("cp.async.cg.shared.global [%0], [%1], 16;"
                 :: "r"(u), "l"(src_gmem) : "memory");
}
#define CP_COMMIT() asm volatile("cp.async.commit_group;" ::: "memory")
#define CP_WAIT(n)  asm volatile("cp.async.wait_group %0;" :: "n"(n) : "memory")

// ---------------------------------------------------------------------------
// Smem-free tile transpose: feat [n][64] -> dT tile [k][128].
// Reads: lanes vary n -> 16B chunks, 256B apart (2x amplified, L2-resident).
// Writes: lanes vary n -> fully coalesced 128B rows.
// ---------------------------------------------------------------------------
__device__ __forceinline__ void tile_transpose(const float* __restrict__ feat,
                                               float* __restrict__ dT,
                                               int t, int N)
{
    float* dst = dT + (size_t)t * 8192;
    for (int i = threadIdx.x; i < 2048; i += 256) {
        int n = i & 127, kq = i >> 7;        // kq in [0,16)
        int gn = t * DN + n;
        float4 v = make_float4(0.f, 0.f, 0.f, 0.f);
        if (gn < N) v = *(const float4*)&feat[gn * FEAT + kq * 4];
        dst[(4 * kq + 0) * 128 + n] = v.x;
        dst[(4 * kq + 1) * 128 + n] = v.y;
        dst[(4 * kq + 2) * 128 + n] = v.z;
        dst[(4 * kq + 3) * 128 + n] = v.w;
    }
}

// ---------------------------------------------------------------------------
// Edge histogram: full grid, one edge per thread (max MLP).
// ---------------------------------------------------------------------------
__global__ void hist_kernel(const int* __restrict__ dst, int E)
{
    int e = blockIdx.x * blockDim.x + threadIdx.x;
    if (e < E) atomicAdd(&g_cnt[dst[e]], 1);
}

// Software grid barrier over the first nb blocks (co-resident: bid 0..48).
__device__ __forceinline__ void grid_bar(int target)
{
    __syncthreads();
    if (threadIdx.x == 0) {
        __threadfence();
        atomicAdd(&g_bar, 1);
        while (atomicAdd(&g_bar, 0) < target) { }
    }
    __syncthreads();
}

// ---------------------------------------------------------------------------
// Scan + fill + transposes: blocks [0,nb) do the CSR scan/fill (proven R12
// logic; zeroes g_cnt -> invariant restore; block 0 resets g_bar). Extra
// blocks [nb, nb+NT) transpose x tiles -> g_xT; [nb+NT, nb+NT+6) transpose
// weights -> g_wT. Extra blocks never touch the grid barrier.
// ---------------------------------------------------------------------------
__global__ void scanfill_kernel(const int* __restrict__ src,
                                const int* __restrict__ dst,
                                int N, int E, int nb, int NT,
                                const float* __restrict__ x,
                                const float* __restrict__ w0, const float* __restrict__ w1,
                                const float* __restrict__ w2, const float* __restrict__ w3,
                                const float* __restrict__ w4, const float* __restrict__ w5)
{
    __shared__ int s_sum[256];
    int t = threadIdx.x;
    int b = blockIdx.x;

    if (b >= nb) {
        int tt = b - nb;
        if (tt < NT) {
            tile_transpose(x, g_xT, tt, N);
        } else {
            int m = tt - NT;      // weight transpose 0..5, writes coalesced in d
            if (m < 6) {
                const float* w = (m == 0) ? w0 : (m == 1) ? w1 : (m == 2) ? w2
                               : (m == 3) ? w3 : (m == 4) ? w4 : w5;
                for (int i = t; i < 4096; i += 256) {
                    int k = i >> 6, d = i & 63;
                    g_wT[m * 4096 + k * 64 + d] = w[d * 64 + k];
                }
            }
        }
        return;
    }

    int base = b * SCAN_CHUNK + t * 8;
    int v[8], tot = 0;
#pragma unroll
    for (int j = 0; j < 8; j++) {
        int idx = base + j;
        if (idx < N) { v[j] = g_cnt[idx]; g_cnt[idx] = 0; }
        else v[j] = 0;
        tot += v[j];
    }
    s_sum[t] = tot;
    __syncthreads();
    for (int off = 1; off < 256; off <<= 1) {
        int xv = (t >= off) ? s_sum[t - off] : 0;
        __syncthreads();
        s_sum[t] += xv;
        __syncthreads();
    }
    if (t == 255) g_bsum[b] = s_sum[255];
    int run = s_sum[t] - tot;

    grid_bar(nb);

    int bpre = 0;
    for (int bb = 0; bb < b; bb++) bpre += g_bsum[bb];
    run += bpre;
#pragma unroll
    for (int j = 0; j < 8; j++) {
        int idx = base + j;
        if (idx < N) { g_off[idx] = run; g_cur[idx] = run; }
        run += v[j];
    }
    if (b == nb - 1 && t == 255) g_off[N] = E;

    grid_bar(2 * nb);

    int tg = b * blockDim.x + t;
    int T  = nb * blockDim.x;
    for (int eb = tg * 8; eb < E; eb += T * 8) {
#pragma unroll
        for (int j = 0; j < 8; j++) {
            int e = eb + j;
            if (e < E) {
                int p = atomicAdd(&g_cur[dst[e]], 1);
                g_csr_src[p] = src[e];
            }
        }
    }
    if (b == 0 && t == 0) g_bar = 0;   // restore invariant
}

// ---------------------------------------------------------------------------
// Aggregate (R12-proven): 8 warps/block = 8 nodes; lane covers feats (2l,2l+1)
// as float2 (~95% of L2 roofline). Writes mean TRANSPOSED into g_aggT tiles
// via a small bank-safe smem bounce. Layer 1: extra blocks [ablocks, +NT)
// transpose g_h1 -> g_h1T, overlapped with the gather.
// ---------------------------------------------------------------------------
__global__ void agg_kernel(const float* __restrict__ x, int N, int layer, int ablocks)
{
    __shared__ float s[64 * 9];
    int b = blockIdx.x;

    if (b >= ablocks) {               // layer-1 h1 transpose blocks
        tile_transpose(g_h1, g_h1T, b - ablocks, N);
        return;
    }

    int warp = threadIdx.x >> 5;
    int lane = threadIdx.x & 31;
    int node = b * 8 + warp;
    const float2* h2 = (const float2*)(layer ? g_h1 : x);

    float ax = 0.f, ay = 0.f;
    int deg = 0;
    if (node < N) {
        int start = g_off[node];
        deg = g_off[node + 1] - start;
        int i = 0;
        for (; i + 8 <= deg; i += 8) {
            int sidx[8];
#pragma unroll
            for (int j = 0; j < 8; j++) sidx[j] = g_csr_src[start + i + j];
            float2 v[8];
#pragma unroll
            for (int j = 0; j < 8; j++) v[j] = h2[sidx[j] * 32 + lane];
            ax += ((v[0].x + v[1].x) + (v[2].x + v[3].x))
                + ((v[4].x + v[5].x) + (v[6].x + v[7].x));
            ay += ((v[0].y + v[1].y) + (v[2].y + v[3].y))
                + ((v[4].y + v[5].y) + (v[6].y + v[7].y));
        }
        for (; i < deg; i++) {
            int sidx = g_csr_src[start + i];
            float2 v = h2[sidx * 32 + lane];
            ax += v.x; ay += v.y;
        }
    }
    float inv = 1.f / fmaxf((float)deg, 1.f);
    s[(2 * lane) * 9 + warp]     = ax * inv;
    s[(2 * lane + 1) * 9 + warp] = ay * inv;
    __syncthreads();

    int nbase = b * 8;
    int tile  = nbase >> 7;
    int nb2   = nbase & 127;
    float* dst = g_aggT + (size_t)tile * 8192;
    for (int i = threadIdx.x; i < 512; i += 256) {
        int k = i >> 3, n = i & 7;
        dst[k * 128 + nb2 + n] = s[k * 9 + n];
    }
}

// ---------------------------------------------------------------------------
// Dense phase (R12-proven, 57.8us): all inputs pre-transposed -> staging is
// pure cp.async, double-buffered (act 2x32KB + w 2x16KB = 96KB, 2 blocks/SM).
// Thread tile 4d x 8n, fma.rn.f32x2 k-loop, conflict-free strides 128/64.
// Phases: agg@wl -> h@wr -> +bl,PReLU (regs) -> x@ws -> +bs.
// ---------------------------------------------------------------------------
__device__ __forceinline__ void dense_compute(const float* __restrict__ act,
                                              const float* __restrict__ w,
                                              ull acc[4][4], int d0, int n0)
{
#pragma unroll 4
    for (int k = 0; k < 64; k++) {
        float4 w4 = *(const float4*)&w[k * 64 + d0];
        ull wd[4];
        wd[0] = dup2(w4.x); wd[1] = dup2(w4.y);
        wd[2] = dup2(w4.z); wd[3] = dup2(w4.w);
        longlong2 p01 = *(const longlong2*)&act[k * 128 + n0];
        longlong2 p23 = *(const longlong2*)&act[k * 128 + n0 + 4];
        ull av[4];
        av[0] = (ull)p01.x; av[1] = (ull)p01.y;
        av[2] = (ull)p23.x; av[3] = (ull)p23.y;
#pragma unroll
        for (int dd = 0; dd < 4; dd++)
#pragma unroll
            for (int p = 0; p < 4; p++)
                fma2(acc[dd][p], av[p], wd[dd]);
    }
}

__global__ void __launch_bounds__(256, 2) dense_kernel(
    const float* __restrict__ x,
    const float* __restrict__ b_l, const float* __restrict__ b_skip,
    const float* __restrict__ a,
    float* __restrict__ out, int N, int layer)
{
    extern __shared__ __align__(16) float sm[];
    float* actA = sm;                  // [64][128]
    float* actB = sm + 8192;
    float* wA   = sm + 16384;          // [64][64]
    float* wB   = sm + 16384 + 4096;

    int tid  = threadIdx.x;
    int base = blockIdx.x * DN;
    int d0   = (tid & 15) * 4;
    int n0   = (tid >> 4) * 8;

    const float* aT = g_aggT + (size_t)blockIdx.x * 8192;
    const float* xT = g_xT   + (size_t)blockIdx.x * 8192;
    const float* hT = layer ? (g_h1T + (size_t)blockIdx.x * 8192) : xT;
    const float* wb = g_wT + layer * 3 * 4096;

    // prologue: stage p0 and p1
    for (int i = tid; i < 2048; i += 256) cp16(&actA[i * 4], &aT[i * 4]);
    for (int i = tid; i < 1024; i += 256) cp16(&wA[i * 4], &wb[i * 4]);
    CP_COMMIT();                                            // g1
    for (int i = tid; i < 2048; i += 256) cp16(&actB[i * 4], &hT[i * 4]);
    for (int i = tid; i < 1024; i += 256) cp16(&wB[i * 4], &wb[4096 + i * 4]);
    CP_COMMIT();                                            // g2

    float bl[4], bs[4], apar[4];
#pragma unroll
    for (int dd = 0; dd < 4; dd++) {
        bl[dd]   = b_l[d0 + dd];
        bs[dd]   = b_skip[d0 + dd];
        apar[dd] = a[d0 + dd];
    }

    ull acc[4][4];
#pragma unroll
    for (int dd = 0; dd < 4; dd++)
#pragma unroll
        for (int p = 0; p < 4; p++) acc[dd][p] = 0ULL;

    // ---- phase 0: agg @ wl ----
    CP_WAIT(1);
    __syncthreads();
    dense_compute(actA, wA, acc, d0, n0);
    __syncthreads();     // all reads of actA/wA done before g3 overwrites

    // stage p2 (layer0 reuses actB = x; layer1 restages actA with xT)
    if (layer) {
        for (int i = tid; i < 2048; i += 256) cp16(&actA[i * 4], &xT[i * 4]);
    }
    for (int i = tid; i < 1024; i += 256) cp16(&wA[i * 4], &wb[8192 + i * 4]);
    CP_COMMIT();                                            // g3

    // ---- phase 1: h @ wr ----
    CP_WAIT(1);
    __syncthreads();
    dense_compute(actB, wB, acc, d0, n0);

    // mid-epilogue in registers: acc = PReLU(acc + bl)
#pragma unroll
    for (int dd = 0; dd < 4; dd++)
#pragma unroll
        for (int p = 0; p < 4; p++) {
            float lo, hi;
            unpk(lo, hi, acc[dd][p]);
            lo += bl[dd]; hi += bl[dd];
            lo = (lo >= 0.f) ? lo : apar[dd] * lo;
            hi = (hi >= 0.f) ? hi : apar[dd] * hi;
            acc[dd][p] = pk2(lo, hi);
        }

    // ---- phase 2: x @ ws ----
    CP_WAIT(0);
    __syncthreads();
    dense_compute(layer ? actA : actB, wA, acc, d0, n0);

    // epilogue: out = acc + bs (natural layout, float4)
    float* dstp = layer ? out : g_h1;
    float f[4][8];
#pragma unroll
    for (int dd = 0; dd < 4; dd++)
#pragma unroll
        for (int p = 0; p < 4; p++)
            unpk(f[dd][2 * p], f[dd][2 * p + 1], acc[dd][p]);
#pragma unroll
    for (int j = 0; j < 8; j++) {
        int gn = base + n0 + j;
        if (gn < N) {
            float4 v;
            v.x = f[0][j] + bs[0];
            v.y = f[1][j] + bs[1];
            v.z = f[2][j] + bs[2];
            v.w = f[3][j] + bs[3];
            *(float4*)&dstp[gn * FEAT + d0] = v;
        }
    }
}

// ---------------------------------------------------------------------------
// Launch sequence: 6 launches. Index 3 (ncu profiled slot) = dense0.
// ---------------------------------------------------------------------------
extern "C" void kernel_launch(void* const* d_in, const int* in_sizes, int n_in,
                              void* d_out, int out_size)
{
    const float* x  = (const float*)d_in[0];
    const int*   ei = (const int*)d_in[1];   // int32 (JAX x64 disabled)
    int N = in_sizes[0] / FEAT;
    int E = in_sizes[1] / 2;
    const int* src = ei;
    const int* dst = ei + E;

    const float* w_l0    = (const float*)d_in[2];
    const float* b_l0    = (const float*)d_in[3];
    const float* w_r0    = (const float*)d_in[4];
    const float* w_skip0 = (const float*)d_in[5];
    const float* b_skip0 = (const float*)d_in[6];
    const float* a0      = (const float*)d_in[7];
    const float* w_l1    = (const float*)d_in[8];
    const float* b_l1    = (const float*)d_in[9];
    const float* w_r1    = (const float*)d_in[10];
    const float* w_skip1 = (const float*)d_in[11];
    const float* b_skip1 = (const float*)d_in[12];
    const float* a1      = (const float*)d_in[13];
    float* out = (float*)d_out;

    size_t dsmem = (size_t)(2 * 64 * 128 + 2 * 64 * 64) * sizeof(float); // 98,304 B
    cudaFuncSetAttribute(dense_kernel, cudaFuncAttributeMaxDynamicSharedMemorySize,
                         (int)dsmem);

    int eblocks = (E + 255) / 256;
    int NT      = (N + DN - 1) / DN;                   // 782
    int nb      = (N + SCAN_CHUNK - 1) / SCAN_CHUNK;   // 49
    int ablocks = (N + 7) / 8;                         // 12500

    hist_kernel<<<eblocks, 256>>>(dst, E);                                 // 0
    scanfill_kernel<<<nb + NT + 6, 256>>>(src, dst, N, E, nb, NT, x,       // 1
                                          w_l0, w_r0, w_skip0,
                                          w_l1, w_r1, w_skip1);

    agg_kernel<<<ablocks, 256>>>(x, N, 0, ablocks);                        // 2
    dense_kernel<<<NT, 256, dsmem>>>(x, b_l0, b_skip0, a0, out, N, 0);     // 3 <- profiled

    agg_kernel<<<ablocks + NT, 256>>>(x, N, 1, ablocks);                   // 4
    dense_kernel<<<NT, 256, dsmem>>>(x, b_l1, b_skip1, a1, out, N, 1);     // 5
}